// round 4
// baseline (speedup 1.0000x reference)
#include <cuda_runtime.h>
#include <cstdint>

// ---------------------------------------------------------------------------
// BatchedSequences: scatter concatenated rows S[T,F] into padded out[B,MAX,F],
// zero-filling padding. HBM-roofline copy.
// R4: persistent grid-stride kernel. Warp scan of lengths runs ONCE per block
//     (held in registers); the mainloop is a clean MLP=4 streaming copy.
// ---------------------------------------------------------------------------

#define MAX_B 4096
__device__ int       g_len[MAX_B];
__device__ long long g_off[MAX_B];

// ---- generic fallback path (any B / shapes) --------------------------------
__global__ void build_offsets_kernel(const void* __restrict__ lens_raw,
                                     int B, long long T) {
    if (threadIdx.x == 0) {
        const int* v32 = (const int*)lens_raw;
        long long s = 0;
        for (int i = 0; i < B; ++i) s += (long long)v32[i];
        const bool is32 = (s == T);
        const long long* v64 = (const long long*)lens_raw;
        long long off = 0;
        for (int i = 0; i < B; ++i) {
            long long L = is32 ? (long long)v32[i] : v64[i];
            g_len[i] = (int)L;
            g_off[i] = off;
            off += L;
        }
    }
}

__global__ void __launch_bounds__(256)
pad_scatter_generic(const float4* __restrict__ in4,
                    float4* __restrict__ out4,
                    int total, int F4, int max_sl) {
    int idx = blockIdx.x * blockDim.x + threadIdx.x;
    if (idx >= total) return;
    int c   = idx % F4;
    int row = idx / F4;
    int b   = row / max_sl;
    int p   = row - b * max_sl;
    float4 v = make_float4(0.f, 0.f, 0.f, 0.f);
    if (p < g_len[b])
        v = __ldcs(&in4[(g_off[b] + (long long)p) * F4 + c]);
    __stcs(&out4[idx], v);
}

// ---- fused persistent fast path (B <= 32, F4/MAX powers of two) -------------
// Each block: one warp-scan of the B lengths (int32/int64 auto-detect via
// sum==T probe), results held in registers. Then grid-stride over 1024-f4
// chunks; each chunk has a block-uniform batch index (1024 | MAX*F4), so
// len/off come from two shfl broadcasts. Mainloop: 4 independent float4
// loads (MLP=4) + streaming stores.
template <int F4_LOG2, int MAX_LOG2>
__global__ void __launch_bounds__(256)
fused_pad_scatter(const float4* __restrict__ in4,
                  float4* __restrict__ out4,
                  const void* __restrict__ lens_raw,
                  int B, long long T, int nchunks) {
    constexpr int F4 = 1 << F4_LOG2;
    constexpr unsigned FULL = 0xFFFFFFFFu;

    const int tid  = threadIdx.x;
    const int lane = tid & 31;

    // ---- once per block: lengths + exclusive offsets, in registers ----
    const int* v32 = (const int*)lens_raw;
    int x32 = (lane < B) ? __ldg(&v32[lane]) : 0;
    long long s = (long long)x32;
    #pragma unroll
    for (int d = 16; d; d >>= 1)
        s += __shfl_xor_sync(FULL, s, d);
    int val = x32;
    if (s != T) {                           // warp-uniform: int64 layout
        const long long* v64 = (const long long*)lens_raw;
        val = (lane < B) ? (int)__ldg(&v64[lane]) : 0;
    }
    int incl = val;                          // inclusive warp scan
    #pragma unroll
    for (int d = 1; d < 32; d <<= 1) {
        int y = __shfl_up_sync(FULL, incl, d);
        if (lane >= d) incl += y;
    }
    const int excl = incl - val;             // exclusive offset, per lane

    // ---- grid-stride mainloop over contiguous 1024-f4 chunks ----
    for (int chunk = blockIdx.x; chunk < nchunks; chunk += gridDim.x) {
        const int base = chunk * 1024;
        const int b    = base >> (F4_LOG2 + MAX_LOG2);   // block-uniform
        const int len  = __shfl_sync(FULL, val,  b);
        const int off  = __shfl_sync(FULL, excl, b);

        int   idx[4], p[4];
        float4 v[4];
        #pragma unroll
        for (int k = 0; k < 4; ++k) {
            idx[k] = base + tid + k * 256;
            p[k]   = (idx[k] >> F4_LOG2) & ((1 << MAX_LOG2) - 1);
            v[k]   = make_float4(0.f, 0.f, 0.f, 0.f);
        }
        #pragma unroll
        for (int k = 0; k < 4; ++k) {
            if (p[k] < len) {
                int c = idx[k] & (F4 - 1);
                v[k] = __ldcs(&in4[(off + p[k]) * F4 + c]);
            }
        }
        #pragma unroll
        for (int k = 0; k < 4; ++k)
            __stcs(&out4[idx[k]], v[k]);
    }
}

extern "C" void kernel_launch(void* const* d_in, const int* in_sizes, int n_in,
                              void* d_out, int out_size) {
    const int F  = 512;
    const int F4 = F / 4;                                    // 128
    const int B  = in_sizes[1];
    const long long T = (long long)in_sizes[0] / F;
    const int max_sl = (int)((long long)out_size / ((long long)B * F));
    const int total  = out_size / 4;                         // float4 count

    if (F4 == 128 && max_sl == 4096 && B <= 32 && (total % 1024) == 0) {
        const int nchunks = total / 1024;                    // 16384
        int blocks = 148 * 8;                                // persistent wave
        if (blocks > nchunks) blocks = nchunks;
        fused_pad_scatter<7, 12><<<blocks, 256>>>(
            (const float4*)d_in[0], (float4*)d_out, d_in[1], B, T, nchunks);
    } else {
        build_offsets_kernel<<<1, 32>>>(d_in[1], B, T);
        pad_scatter_generic<<<(total + 255) / 256, 256>>>(
            (const float4*)d_in[0], (float4*)d_out, total, F4, max_sl);
    }
}

// round 5
// speedup vs baseline: 1.1374x; 1.1374x over previous
#include <cuda_runtime.h>
#include <cstdint>

// ---------------------------------------------------------------------------
// BatchedSequences: scatter concatenated rows S[T,F] into padded out[B,MAX,F],
// zero-filling padding. HBM-roofline copy.
// R5: fused one-block-per-chunk (R3 shape — beats persistent loops here),
//     chunk doubled to 2048 float4 (VPT=8, MLP=8 front-batched loads),
//     int32 warp scan once per block.
// ---------------------------------------------------------------------------

#define MAX_B 4096
__device__ int       g_len[MAX_B];
__device__ long long g_off[MAX_B];

// ---- generic fallback path (any B / shapes) --------------------------------
__global__ void build_offsets_kernel(const void* __restrict__ lens_raw,
                                     int B, long long T) {
    if (threadIdx.x == 0) {
        const int* v32 = (const int*)lens_raw;
        long long s = 0;
        for (int i = 0; i < B; ++i) s += (long long)v32[i];
        const bool is32 = (s == T);
        const long long* v64 = (const long long*)lens_raw;
        long long off = 0;
        for (int i = 0; i < B; ++i) {
            long long L = is32 ? (long long)v32[i] : v64[i];
            g_len[i] = (int)L;
            g_off[i] = off;
            off += L;
        }
    }
}

__global__ void __launch_bounds__(256)
pad_scatter_generic(const float4* __restrict__ in4,
                    float4* __restrict__ out4,
                    int total, int F4, int max_sl) {
    int idx = blockIdx.x * blockDim.x + threadIdx.x;
    if (idx >= total) return;
    int c   = idx % F4;
    int row = idx / F4;
    int b   = row / max_sl;
    int p   = row - b * max_sl;
    float4 v = make_float4(0.f, 0.f, 0.f, 0.f);
    if (p < g_len[b])
        v = __ldcs(&in4[(g_off[b] + (long long)p) * F4 + c]);
    __stcs(&out4[idx], v);
}

// ---- fused fast path (B <= 32, F4/MAX powers of two) ------------------------
// One block per 2048 contiguous float4 (256 thr x 8). 2048 | MAX*F4, so the
// batch index b is block-uniform. Each warp lane-loads the B lengths
// (int32/int64 auto-detect via int-sum==T probe), warp-scans for offsets,
// then broadcasts len/off for this block's batch. Mainloop: 8 independent
// float4 loads (MLP=8) + 8 streaming stores, no loop.
template <int F4_LOG2, int MAX_LOG2, int VPT>
__global__ void __launch_bounds__(256)
fused_pad_scatter(const float4* __restrict__ in4,
                  float4* __restrict__ out4,
                  const void* __restrict__ lens_raw,
                  int B, int T) {
    constexpr int F4 = 1 << F4_LOG2;
    constexpr unsigned FULL = 0xFFFFFFFFu;
    constexpr int CHUNK = 256 * VPT;

    const int tid  = threadIdx.x;
    const int lane = tid & 31;
    const int base = (int)blockIdx.x * CHUNK;
    const int b    = base >> (F4_LOG2 + MAX_LOG2);   // block-uniform

    // lengths: int32 view is always in-bounds (B*4 bytes). If the buffer is
    // int64, that view is [L0,0,L1,0,...] whose sum < T -> reload as int64.
    const int* v32 = (const int*)lens_raw;
    int val = (lane < B) ? __ldg(&v32[lane]) : 0;
    int s = val;
    #pragma unroll
    for (int d = 16; d; d >>= 1)
        s += __shfl_xor_sync(FULL, s, d);
    if (s != T) {                            // warp-uniform: int64 layout
        const long long* v64 = (const long long*)lens_raw;
        val = (lane < B) ? (int)__ldg(&v64[lane]) : 0;
    }
    int incl = val;                          // inclusive warp scan
    #pragma unroll
    for (int d = 1; d < 32; d <<= 1) {
        int y = __shfl_up_sync(FULL, incl, d);
        if (lane >= d) incl += y;
    }
    const int len = __shfl_sync(FULL, val,        b);
    const int off = __shfl_sync(FULL, incl - val, b);

    // main copy: VPT independent float4 loads, front-batched (MLP=VPT).
    int   idx[VPT], p[VPT];
    float4 v[VPT];
    #pragma unroll
    for (int k = 0; k < VPT; ++k) {
        idx[k] = base + tid + k * 256;
        p[k]   = (idx[k] >> F4_LOG2) & ((1 << MAX_LOG2) - 1);
        v[k]   = make_float4(0.f, 0.f, 0.f, 0.f);
    }
    #pragma unroll
    for (int k = 0; k < VPT; ++k) {
        if (p[k] < len) {
            int c = idx[k] & (F4 - 1);
            v[k] = __ldcs(&in4[(off + p[k]) * F4 + c]);
        }
    }
    #pragma unroll
    for (int k = 0; k < VPT; ++k)
        __stcs(&out4[idx[k]], v[k]);
}

extern "C" void kernel_launch(void* const* d_in, const int* in_sizes, int n_in,
                              void* d_out, int out_size) {
    const int F  = 512;
    const int F4 = F / 4;                                    // 128
    const int B  = in_sizes[1];
    const long long T = (long long)in_sizes[0] / F;
    const int max_sl = (int)((long long)out_size / ((long long)B * F));
    const int total  = out_size / 4;                         // float4 count

    if (F4 == 128 && max_sl == 4096 && B <= 32 && (total % 2048) == 0 &&
        T <= 0x7FFFFFFFLL) {
        fused_pad_scatter<7, 12, 8><<<total / 2048, 256>>>(
            (const float4*)d_in[0], (float4*)d_out, d_in[1], B, (int)T);
    } else {
        build_offsets_kernel<<<1, 32>>>(d_in[1], B, T);
        pad_scatter_generic<<<(total + 255) / 256, 256>>>(
            (const float4*)d_in[0], (float4*)d_out, total, F4, max_sl);
    }
}

// round 6
// speedup vs baseline: 1.1379x; 1.0004x over previous
#include <cuda_runtime.h>
#include <cstdint>

// ---------------------------------------------------------------------------
// BatchedSequences: scatter concatenated rows S[T,F] into padded out[B,MAX,F],
// zero-filling padding. HBM-roofline copy (plateau ~6.2 TB/s mixed R/W).
// R6: fused single kernel, VPT=4 / 16384 blocks (fastest shape measured).
//     - ballot-based int32/int64 probe (no reduce chain)
//     - contiguous-source insight: chunk copy needs NO row/col math
//     - block-uniform 3-way specialization: full / padding / boundary chunk
// ---------------------------------------------------------------------------

#define MAX_B 4096
__device__ int       g_len[MAX_B];
__device__ long long g_off[MAX_B];

// ---- generic fallback path (any B / shapes) --------------------------------
__global__ void build_offsets_kernel(const void* __restrict__ lens_raw,
                                     int B, long long T) {
    if (threadIdx.x == 0) {
        const int* v32 = (const int*)lens_raw;
        long long s = 0;
        for (int i = 0; i < B; ++i) s += (long long)v32[i];
        const bool is32 = (s == T);
        const long long* v64 = (const long long*)lens_raw;
        long long off = 0;
        for (int i = 0; i < B; ++i) {
            long long L = is32 ? (long long)v32[i] : v64[i];
            g_len[i] = (int)L;
            g_off[i] = off;
            off += L;
        }
    }
}

__global__ void __launch_bounds__(256)
pad_scatter_generic(const float4* __restrict__ in4,
                    float4* __restrict__ out4,
                    int total, int F4, int max_sl) {
    int idx = blockIdx.x * blockDim.x + threadIdx.x;
    if (idx >= total) return;
    int c   = idx % F4;
    int row = idx / F4;
    int b   = row / max_sl;
    int p   = row - b * max_sl;
    float4 v = make_float4(0.f, 0.f, 0.f, 0.f);
    if (p < g_len[b])
        v = __ldcs(&in4[(g_off[b] + (long long)p) * F4 + c]);
    __stcs(&out4[idx], v);
}

// ---- fused fast path (B <= 32, F4/MAX powers of two) ------------------------
// One block per CHUNK=1024 contiguous float4 (= 8 rows of F4=128). CHUNK
// divides MAX*F4, so the batch index is block-uniform and the len boundary
// cuts at most one chunk per batch. Source within a chunk is contiguous:
// src[e] = in4[(off+p0)*F4 + e].
template <int F4_LOG2, int MAX_LOG2, int VPT>
__global__ void __launch_bounds__(256)
fused_pad_scatter(const float4* __restrict__ in4,
                  float4* __restrict__ out4,
                  const void* __restrict__ lens_raw,
                  int B) {
    constexpr unsigned FULL  = 0xFFFFFFFFu;
    constexpr int CHUNK = 256 * VPT;
    constexpr int ROWS  = CHUNK >> F4_LOG2;          // rows per chunk

    const int tid  = threadIdx.x;
    const int lane = tid & 31;
    const int base = (int)blockIdx.x * CHUNK;
    const int b    = base >> (F4_LOG2 + MAX_LOG2);   // block-uniform

    // dtype probe: read first B int32 words (in-bounds for both layouts).
    // int32 lengths are positive -> some odd word nonzero. int64 (LE,
    // values < 2^31) -> odd words are high halves, all zero.
    const int* v32 = (const int*)lens_raw;
    int w = (lane < B) ? __ldg(&v32[lane]) : 0;
    const bool is32 = __ballot_sync(FULL, (lane & 1) && (w != 0)) != 0;
    int val = w;
    if (!is32) {                                     // warp-uniform branch
        const long long* v64 = (const long long*)lens_raw;
        val = (lane < B) ? (int)__ldg(&v64[lane]) : 0;
    }
    int incl = val;                                  // inclusive warp scan
    #pragma unroll
    for (int d = 1; d < 32; d <<= 1) {
        int y = __shfl_up_sync(FULL, incl, d);
        if (lane >= d) incl += y;
    }
    const int len = __shfl_sync(FULL, val,        b);
    const int off = __shfl_sync(FULL, incl - val, b);

    const int p0 = (base >> F4_LOG2) & ((1 << MAX_LOG2) - 1);  // first row
    float4* __restrict__ outp = out4 + base;

    if (p0 >= len) {
        // all-padding chunk: stores only
        const float4 z = make_float4(0.f, 0.f, 0.f, 0.f);
        #pragma unroll
        for (int k = 0; k < VPT; ++k)
            __stcs(&outp[tid + k * 256], z);
    } else {
        const float4* __restrict__ src = in4 + ((off + p0) << F4_LOG2);
        if (p0 + ROWS <= len) {
            // fully valid chunk: straight streaming copy, no predicates
            float4 v[VPT];
            #pragma unroll
            for (int k = 0; k < VPT; ++k)
                v[k] = __ldcs(&src[tid + k * 256]);
            #pragma unroll
            for (int k = 0; k < VPT; ++k)
                __stcs(&outp[tid + k * 256], v[k]);
        } else {
            // boundary chunk (<= 1 per batch): predicated
            const int valid_e = (len - p0) << F4_LOG2;
            #pragma unroll
            for (int k = 0; k < VPT; ++k) {
                const int e = tid + k * 256;
                float4 v = make_float4(0.f, 0.f, 0.f, 0.f);
                if (e < valid_e) v = __ldcs(&src[e]);
                __stcs(&outp[e], v);
            }
        }
    }
}

extern "C" void kernel_launch(void* const* d_in, const int* in_sizes, int n_in,
                              void* d_out, int out_size) {
    const int F  = 512;
    const int F4 = F / 4;                                    // 128
    const int B  = in_sizes[1];
    const long long T = (long long)in_sizes[0] / F;
    const int max_sl = (int)((long long)out_size / ((long long)B * F));
    const int total  = out_size / 4;                         // float4 count

    if (F4 == 128 && max_sl == 4096 && B <= 32 && (total % 1024) == 0 &&
        T <= 0x7FFFFFFFLL) {
        fused_pad_scatter<7, 12, 4><<<total / 1024, 256>>>(
            (const float4*)d_in[0], (float4*)d_out, d_in[1], B);
    } else {
        build_offsets_kernel<<<1, 32>>>(d_in[1], B, T);
        pad_scatter_generic<<<(total + 255) / 256, 256>>>(
            (const float4*)d_in[0], (float4*)d_out, total, F4, max_sl);
    }
}